// round 15
// baseline (speedup 1.0000x reference)
#include <cuda_runtime.h>
#include <cuda_fp16.h>
#include <cstdint>

// Problem constants
#define BB   8
#define CC   256
#define HH   64
#define WWW  64
#define HWSZ 4096
#define K2C  9
#define OO   256
#define KTOT (K2C * CC)          // 2304
#define NKB  (KTOT / 64)         // 36 slabs of K=64
#define SW   36                  // B smem row stride in fp16x2 words

// 3-stage dynamic smem pipeline
#define B_STG 18432u             // 128*36*4
#define A_STG 16384u
#define BS_OFF 0u                // 3 * 18432 = 55296
#define AS_OFF 55296u            // 3 * 16384 = 49152
#define DSMEM_BYTES 104448

// Scratch (device globals — no allocation allowed)
__device__ __half   g_xTh[BB * HWSZ * CC];    // x transposed fp16: [B][HW][C]
__device__ uint32_t g_WkFH[OO * KTOT / 2];    // weights fp16x2, mma-fragment order
__device__ int4     g_off[BB * K2C * HWSZ];   // 4 corner BYTE offsets (idx*CC*2)
__device__ uint4    g_wh[BB * K2C * HWSZ];    // 4 bilinear weights as half2 bcast

// ---------------------------------------------------------------------------
// asm helpers
// ---------------------------------------------------------------------------
__device__ __forceinline__ void cpasync16(uint32_t dst, const void* src) {
    asm volatile("cp.async.cg.shared.global [%0], [%1], 16;" :: "r"(dst), "l"(src));
}
__device__ __forceinline__ void cpasync_commit() {
    asm volatile("cp.async.commit_group;" ::: "memory");
}
__device__ __forceinline__ void cpasync_wait0() {
    asm volatile("cp.async.wait_group 0;" ::: "memory");
}
__device__ __forceinline__ void sts64(uint32_t a, uint32_t v0, uint32_t v1) {
    asm volatile("st.shared.v2.b32 [%0], {%1,%2};" :: "r"(a), "r"(v0), "r"(v1));
}
__device__ __forceinline__ uint4 lds128(uint32_t a) {
    uint4 v;
    asm volatile("ld.shared.v4.b32 {%0,%1,%2,%3}, [%4];"
                 : "=r"(v.x), "=r"(v.y), "=r"(v.z), "=r"(v.w) : "r"(a));
    return v;
}
__device__ __forceinline__ void ldmx4(uint32_t& r0, uint32_t& r1, uint32_t& r2,
                                      uint32_t& r3, uint32_t a) {
    asm volatile("ldmatrix.sync.aligned.m8n8.x4.shared.b16 {%0,%1,%2,%3}, [%4];"
                 : "=r"(r0), "=r"(r1), "=r"(r2), "=r"(r3) : "r"(a));
}
#define BAR_SYNC(id, cnt) \
    asm volatile("bar.sync %0, %1;" :: "r"(id), "r"(cnt) : "memory")
#define BAR_ARRIVE(id, cnt) \
    asm volatile("bar.arrive %0, %1;" :: "r"(id), "r"(cnt) : "memory")

// ---------------------------------------------------------------------------
// Kernel A: transpose x [B][C][HW] -> g_xTh [B][HW][C] (fp16)
// ---------------------------------------------------------------------------
__global__ void transpose_x_kernel(const float* __restrict__ x) {
    __shared__ __align__(16) float tile[32][33];
    int b   = blockIdx.z;
    int hw0 = blockIdx.x * 32;
    int c0  = blockIdx.y * 32;
    int tx = threadIdx.x, ty = threadIdx.y;
    const float* xb = x + (size_t)b * CC * HWSZ;
#pragma unroll
    for (int i = 0; i < 4; i++) {
        int c = c0 + ty + i * 8;
        tile[ty + i * 8][tx] = xb[(size_t)c * HWSZ + hw0 + tx];
    }
    __syncthreads();
    __half* xt = g_xTh + (size_t)b * HWSZ * CC;
#pragma unroll
    for (int i = 0; i < 4; i++) {
        int hw = hw0 + ty + i * 8;
        xt[(size_t)hw * CC + c0 + tx] = __float2half(tile[tx][ty + i * 8]);
    }
}

// ---------------------------------------------------------------------------
// Kernel B: build bilinear meta (byte offsets + half2-broadcast weights)
// ---------------------------------------------------------------------------
__device__ __forceinline__ int clamp63(int v) { return v < 0 ? 0 : (v > 63 ? 63 : v); }

__global__ void build_meta_kernel(const float* __restrict__ offset) {
    int t = blockIdx.x * blockDim.x + threadIdx.x;
    int p  = t & (HWSZ - 1);
    int bk = t >> 12;
    int k2 = bk % K2C;
    int b  = bk / K2C;
    int ho = p >> 6, wo = p & 63;
    int ky = k2 / 3, kx = k2 % 3;
    const float* ob = offset + (size_t)b * 2 * K2C * HWSZ;
    float dy = ob[(size_t)(k2 * 2 + 0) * HWSZ + p];
    float dx = ob[(size_t)(k2 * 2 + 1) * HWSZ + p];
    float py = (float)(ho - 1 + ky) + dy;
    float px = (float)(wo - 1 + kx) + dx;
    float y0f = floorf(py), x0f = floorf(px);
    int   y0  = (int)y0f,  x0  = (int)x0f;
    float fy = py - y0f,   fx = px - x0f;
    int ys[2] = { y0, y0 + 1 }, xs[2] = { x0, x0 + 1 };
    float wy[2] = { 1.0f - fy, fy }, wx[2] = { 1.0f - fx, fx };
    int off[4]; uint32_t wh[4];
#pragma unroll
    for (int j = 0; j < 4; j++) {
        int yy = ys[j >> 1], xx = xs[j & 1];
        bool valid = (yy >= 0) && (yy < HH) && (xx >= 0) && (xx < WWW);
        float w = valid ? (wy[j >> 1] * wx[j & 1]) : 0.0f;
        __half2 h = __float2half2_rn(w);
        wh[j]  = *(const uint32_t*)&h;
        off[j] = (clamp63(yy) * WWW + clamp63(xx)) * (CC * 2);   // bytes
    }
    g_off[t] = make_int4(off[0], off[1], off[2], off[3]);
    g_wh[t]  = make_uint4(wh[0], wh[1], wh[2], wh[3]);
}

// ---------------------------------------------------------------------------
// Kernel B2: weight -> g_WkFH fp16x2 in m16n8k16 fragment order.
// ---------------------------------------------------------------------------
__global__ void prep_w_kernel(const float* __restrict__ weight) {
    int t = blockIdx.x * blockDim.x + threadIdx.x;   // < OO*KTOT/2
    int e    = t & 3;
    int lane = (t >> 2) & 31;
    int ks   = (t >> 7) & 3;
    int mi   = (t >> 9) & 3;
    int kb   = (t >> 11) % NKB;
    int half = (t >> 11) / NKB;
    int wm = half & 1, ohalf = half >> 1;
    int row = wm * 64 + mi * 16 + (lane >> 2) + (e & 1) * 8;
    int kg  = kb * 64 + ks * 16 + (e >> 1) * 8 + 2 * (lane & 3);
    int o  = ohalf * 128 + row;
    int k2 = kg >> 8, c = kg & 255;
    float w0 = weight[((size_t)o * CC + c) * K2C + k2];
    float w1 = weight[((size_t)o * CC + c + 1) * K2C + k2];
    __half2 h = __floats2half2_rn(w0, w1);
    g_WkFH[t] = *(const uint32_t*)&h;
}

// ---------------------------------------------------------------------------
// Kernel C: warp-specialized. Warps 0-7 consume (mma), warps 8-15 produce
//   (gather + combine + STS + cp.async A + meta). 3-stage smem pipeline,
//   named-barrier ping-pong: full[s]=1+s, empty[s]=4+s, producer meta=7.
// ---------------------------------------------------------------------------
__global__ __launch_bounds__(512, 1)
void dconv_mma_kernel(float* __restrict__ out) {
    extern __shared__ char dsm[];
    __shared__ __align__(16) int4  sOff[128];
    __shared__ __align__(16) uint4 sWh[128];

    uint32_t sb = (uint32_t)__cvta_generic_to_shared(dsm);

    int tid  = threadIdx.x;
    int lane = tid & 31;
    int wid  = tid >> 5;
    int bx = blockIdx.x;
    int b  = bx >> 6;
    int ohalf = (bx >> 5) & 1;
    int o0 = ohalf * 128;
    int p0 = (bx & 31) * 128;

    const __half* xTb = g_xTh + (size_t)b * HWSZ * CC;

    if (wid < 8) {
        // =================== CONSUMER: pure MMA =====================
        int wm = wid & 1;
        int wn = wid >> 1;

        float acc[4][4][4];
#pragma unroll
        for (int mi = 0; mi < 4; mi++)
#pragma unroll
            for (int ni = 0; ni < 4; ni++)
#pragma unroll
                for (int r = 0; r < 4; r++) acc[mi][ni][r] = 0.0f;

        uint32_t aBase = sb + AS_OFF + (uint32_t)(wm * 8192) + (uint32_t)lane * 16;
        uint32_t bLdmBase = sb + BS_OFF + (uint32_t)(
            ((wn * 32 + ((lane >> 4) & 1) * 8 + (lane & 7)) * SW +
             ((lane >> 3) & 1) * 4) * 4);

        int s = 0;
        for (int kb = 0; kb < NKB; kb++) {
            BAR_SYNC(1 + s, 512);            // wait stage s full
            uint32_t aB = aBase + (uint32_t)s * A_STG;
            uint32_t bB = bLdmBase + (uint32_t)s * B_STG;
#pragma unroll
            for (int ks = 0; ks < 4; ks++) {
                uint32_t bfr[4][2];
#pragma unroll
                for (int np = 0; np < 2; np++)
                    ldmx4(bfr[np * 2][0], bfr[np * 2][1],
                          bfr[np * 2 + 1][0], bfr[np * 2 + 1][1],
                          bB + (uint32_t)(np * 2304 + ks * 32));
#pragma unroll
                for (int mi = 0; mi < 4; mi++) {
                    uint4 afr = lds128(aB + (uint32_t)(((mi * 4 + ks) * 32) * 16));
#pragma unroll
                    for (int ni = 0; ni < 4; ni++) {
                        asm volatile(
                            "mma.sync.aligned.m16n8k16.row.col.f32.f16.f16.f32 "
                            "{%0,%1,%2,%3}, {%4,%5,%6,%7}, {%8,%9}, {%0,%1,%2,%3};"
                            : "+f"(acc[mi][ni][0]), "+f"(acc[mi][ni][1]),
                              "+f"(acc[mi][ni][2]), "+f"(acc[mi][ni][3])
                            : "r"(afr.x), "r"(afr.y), "r"(afr.z), "r"(afr.w),
                              "r"(bfr[ni][0]), "r"(bfr[ni][1]));
                    }
                }
            }
            BAR_ARRIVE(4 + s, 512);          // stage s now empty
            s = (s == 2) ? 0 : s + 1;
        }

        // ---- epilogue
        int r  = lane >> 2;
        int cl = (lane & 3) * 2;
#pragma unroll
        for (int mi = 0; mi < 4; mi++) {
            int m = wm * 64 + mi * 16 + r;
            float* op = out + ((size_t)b * OO + (o0 + m)) * HWSZ + p0;
#pragma unroll
            for (int ni = 0; ni < 4; ni++) {
                int n = wn * 32 + ni * 8 + cl;
                *(float2*)(op + n) =
                    make_float2(acc[mi][ni][0], acc[mi][ni][1]);
                *(float2*)(op + 8 * HWSZ + n) =
                    make_float2(acc[mi][ni][2], acc[mi][ni][3]);
            }
        }
    } else {
        // =================== PRODUCER: gather + A ====================
        int pt = tid - 256;                  // 0..255
        int pw = (wid - 8);                  // producer warp 0..7
        int hsel = lane >> 4;
        int lidx = lane & 15;

        const uint4* asrc_base = (const uint4*)g_WkFH
            + (size_t)(ohalf * 2 + (pt >> 7)) * NKB * 512 + (pt & 127) * 4;
        uint32_t adst_base = sb + AS_OFF +
            (uint32_t)(((pt >> 7) * 512 + (pt & 127) * 4) * 16);
        uint32_t bStsBase = sb + BS_OFF +
            (uint32_t)((((pw * 16 + hsel) * SW) + 2 * lidx) * 4);

        int s = 0;
        for (int kb = 0; kb < NKB; kb++) {
            if (kb >= 3) BAR_SYNC(4 + s, 512);      // wait stage s empty
            if ((kb & 3) == 0) {
                int k2 = kb >> 2;
                BAR_SYNC(7, 256);                   // all producers past old meta
                if (pt < 128) {
                    size_t mi0 = ((size_t)(b * K2C + k2) * HWSZ) + p0 + pt;
                    sOff[pt] = g_off[mi0];
                    sWh[pt]  = g_wh[mi0];
                }
                BAR_SYNC(7, 256);                   // meta visible
            }

            // A tile for this slab via cp.async
            {
                const uint4* asrc = asrc_base + (size_t)kb * 512;
                uint32_t adst = adst_base + (uint32_t)s * A_STG;
#pragma unroll
                for (int it = 0; it < 4; it++)
                    cpasync16(adst + it * 16, asrc + it);
                cpasync_commit();
            }

            // gather + combine + STS (two halves of 4 pixel-pairs)
            const char* xc = (const char*)(xTb + (kb & 3) * 64) + lidx * 8;
            uint32_t sB = bStsBase + (uint32_t)s * B_STG;
#pragma unroll
            for (int hk = 0; hk < 2; hk++) {
                uint2 raw[16];
#pragma unroll
                for (int qq = 0; qq < 4; qq++) {
                    int p = pw * 16 + 2 * (hk * 4 + qq) + hsel;
                    int4 ov = sOff[p];
                    raw[qq * 4 + 0] = *(const uint2*)(xc + ov.x);
                    raw[qq * 4 + 1] = *(const uint2*)(xc + ov.y);
                    raw[qq * 4 + 2] = *(const uint2*)(xc + ov.z);
                    raw[qq * 4 + 3] = *(const uint2*)(xc + ov.w);
                }
#pragma unroll
                for (int qq = 0; qq < 4; qq++) {
                    int q = hk * 4 + qq;
                    int p = pw * 16 + 2 * q + hsel;
                    uint4 wv = sWh[p];
                    uint2 u0 = raw[qq * 4 + 0];
                    uint2 u1 = raw[qq * 4 + 1];
                    uint2 u2 = raw[qq * 4 + 2];
                    uint2 u3 = raw[qq * 4 + 3];
                    __half2 a0 = __hmul2(*(const __half2*)&wv.x, *(const __half2*)&u0.x);
                    __half2 a1 = __hmul2(*(const __half2*)&wv.x, *(const __half2*)&u0.y);
                    a0 = __hfma2(*(const __half2*)&wv.y, *(const __half2*)&u1.x, a0);
                    a1 = __hfma2(*(const __half2*)&wv.y, *(const __half2*)&u1.y, a1);
                    a0 = __hfma2(*(const __half2*)&wv.z, *(const __half2*)&u2.x, a0);
                    a1 = __hfma2(*(const __half2*)&wv.z, *(const __half2*)&u2.y, a1);
                    a0 = __hfma2(*(const __half2*)&wv.w, *(const __half2*)&u3.x, a0);
                    a1 = __hfma2(*(const __half2*)&wv.w, *(const __half2*)&u3.y, a1);
                    sts64(sB + q * (2 * SW * 4),
                          *(const uint32_t*)&a0, *(const uint32_t*)&a1);
                }
            }

            cpasync_wait0();                 // A landed in smem
            __threadfence_block();           // publish STS + cp.async data
            BAR_ARRIVE(1 + s, 512);          // stage s full
            s = (s == 2) ? 0 : s + 1;
        }
    }
}

// ---------------------------------------------------------------------------
extern "C" void kernel_launch(void* const* d_in, const int* in_sizes, int n_in,
                              void* d_out, int out_size) {
    const float* x      = (const float*)d_in[0];
    const float* offset = (const float*)d_in[1];
    const float* weight = (const float*)d_in[2];
    float* out = (float*)d_out;

    cudaFuncSetAttribute(dconv_mma_kernel,
                         cudaFuncAttributeMaxDynamicSharedMemorySize, DSMEM_BYTES);

    transpose_x_kernel<<<dim3(HWSZ / 32, CC / 32, BB), dim3(32, 8)>>>(x);
    build_meta_kernel<<<(BB * K2C * HWSZ) / 256, 256>>>(offset);
    prep_w_kernel<<<(OO * KTOT / 2) / 256, 256>>>(weight);
    dconv_mma_kernel<<<BB * 64, 512, DSMEM_BYTES>>>(out);
}

// round 16
// speedup vs baseline: 1.2140x; 1.2140x over previous
#include <cuda_runtime.h>
#include <cuda_fp16.h>
#include <cstdint>

// Problem constants
#define BB   8
#define CC   256
#define HH   64
#define WWW  64
#define HWSZ 4096
#define K2C  9
#define OO   256
#define KTOT (K2C * CC)          // 2304
#define NKB  (KTOT / 64)         // 36 slabs of K=64
#define SW   36                  // B smem row stride in fp16x2 words

// Dynamic smem layout (bytes): B 2*18432, A 2*32768
#define BS_OFF   0u
#define AS_OFF   36864u
#define A_STG    32768u
#define DSMEM_BYTES 102400

// Scratch (device globals — no allocation allowed)
__device__ __half   g_xTh[BB * HWSZ * CC];    // x transposed fp16: [B][HW][C]
__device__ uint32_t g_WkFH[OO * KTOT / 2];    // weights fp16x2, mma-fragment order
__device__ int4     g_off[BB * K2C * HWSZ];   // 4 corner BYTE offsets (idx*CC*2)
__device__ uint4    g_wh[BB * K2C * HWSZ];    // 4 bilinear weights as half2 bcast

// ---------------------------------------------------------------------------
// asm helpers
// ---------------------------------------------------------------------------
__device__ __forceinline__ void cpasync16(uint32_t dst, const void* src) {
    asm volatile("cp.async.cg.shared.global [%0], [%1], 16;" :: "r"(dst), "l"(src));
}
__device__ __forceinline__ void cpasync_commit() {
    asm volatile("cp.async.commit_group;" ::: "memory");
}
__device__ __forceinline__ void cpasync_wait0() {
    asm volatile("cp.async.wait_group 0;" ::: "memory");
}
__device__ __forceinline__ void sts64(uint32_t a, uint32_t v0, uint32_t v1) {
    asm volatile("st.shared.v2.b32 [%0], {%1,%2};" :: "r"(a), "r"(v0), "r"(v1));
}
__device__ __forceinline__ uint4 lds128(uint32_t a) {
    uint4 v;
    asm volatile("ld.shared.v4.b32 {%0,%1,%2,%3}, [%4];"
                 : "=r"(v.x), "=r"(v.y), "=r"(v.z), "=r"(v.w) : "r"(a));
    return v;
}
__device__ __forceinline__ void ldmx4(uint32_t& r0, uint32_t& r1, uint32_t& r2,
                                      uint32_t& r3, uint32_t a) {
    asm volatile("ldmatrix.sync.aligned.m8n8.x4.shared.b16 {%0,%1,%2,%3}, [%4];"
                 : "=r"(r0), "=r"(r1), "=r"(r2), "=r"(r3) : "r"(a));
}

// ---------------------------------------------------------------------------
// Kernel A: transpose x [B][C][HW] -> g_xTh [B][HW][C] (fp16)
// ---------------------------------------------------------------------------
__global__ void transpose_x_kernel(const float* __restrict__ x) {
    __shared__ __align__(16) float tile[32][33];
    int b   = blockIdx.z;
    int hw0 = blockIdx.x * 32;
    int c0  = blockIdx.y * 32;
    int tx = threadIdx.x, ty = threadIdx.y;
    const float* xb = x + (size_t)b * CC * HWSZ;
#pragma unroll
    for (int i = 0; i < 4; i++) {
        int c = c0 + ty + i * 8;
        tile[ty + i * 8][tx] = xb[(size_t)c * HWSZ + hw0 + tx];
    }
    __syncthreads();
    __half* xt = g_xTh + (size_t)b * HWSZ * CC;
#pragma unroll
    for (int i = 0; i < 4; i++) {
        int hw = hw0 + ty + i * 8;
        xt[(size_t)hw * CC + c0 + tx] = __float2half(tile[tx][ty + i * 8]);
    }
}

// ---------------------------------------------------------------------------
// Kernel B: build bilinear meta (byte offsets + half2-broadcast weights)
// ---------------------------------------------------------------------------
__device__ __forceinline__ int clamp63(int v) { return v < 0 ? 0 : (v > 63 ? 63 : v); }

__global__ void build_meta_kernel(const float* __restrict__ offset) {
    int t = blockIdx.x * blockDim.x + threadIdx.x;
    int p  = t & (HWSZ - 1);
    int bk = t >> 12;
    int k2 = bk % K2C;
    int b  = bk / K2C;
    int ho = p >> 6, wo = p & 63;
    int ky = k2 / 3, kx = k2 % 3;
    const float* ob = offset + (size_t)b * 2 * K2C * HWSZ;
    float dy = ob[(size_t)(k2 * 2 + 0) * HWSZ + p];
    float dx = ob[(size_t)(k2 * 2 + 1) * HWSZ + p];
    float py = (float)(ho - 1 + ky) + dy;
    float px = (float)(wo - 1 + kx) + dx;
    float y0f = floorf(py), x0f = floorf(px);
    int   y0  = (int)y0f,  x0  = (int)x0f;
    float fy = py - y0f,   fx = px - x0f;
    int ys[2] = { y0, y0 + 1 }, xs[2] = { x0, x0 + 1 };
    float wy[2] = { 1.0f - fy, fy }, wx[2] = { 1.0f - fx, fx };
    int off[4]; uint32_t wh[4];
#pragma unroll
    for (int j = 0; j < 4; j++) {
        int yy = ys[j >> 1], xx = xs[j & 1];
        bool valid = (yy >= 0) && (yy < HH) && (xx >= 0) && (xx < WWW);
        float w = valid ? (wy[j >> 1] * wx[j & 1]) : 0.0f;
        __half2 h = __float2half2_rn(w);
        wh[j]  = *(const uint32_t*)&h;
        off[j] = (clamp63(yy) * WWW + clamp63(xx)) * (CC * 2);   // bytes
    }
    g_off[t] = make_int4(off[0], off[1], off[2], off[3]);
    g_wh[t]  = make_uint4(wh[0], wh[1], wh[2], wh[3]);
}

// ---------------------------------------------------------------------------
// Kernel B2: weight -> g_WkFH fp16x2 in m16n8k16 fragment order.
//   Block layout: [half(0..3)][kb] x 2048 uint32; half = M-quarter (64 rows).
// ---------------------------------------------------------------------------
__global__ void prep_w_kernel(const float* __restrict__ weight) {
    int t = blockIdx.x * blockDim.x + threadIdx.x;   // < OO*KTOT/2
    int e    = t & 3;
    int lane = (t >> 2) & 31;
    int ks   = (t >> 7) & 3;
    int mi   = (t >> 9) & 3;
    int kb   = (t >> 11) % NKB;
    int half = (t >> 11) / NKB;                      // M-quarter 0..3
    int row = mi * 16 + (lane >> 2) + (e & 1) * 8;   // within quarter
    int kg  = kb * 64 + ks * 16 + (e >> 1) * 8 + 2 * (lane & 3);
    int o  = half * 64 + row;
    int k2 = kg >> 8, c = kg & 255;
    float w0 = weight[((size_t)o * CC + c) * K2C + k2];
    float w1 = weight[((size_t)o * CC + c + 1) * K2C + k2];
    __half2 h = __floats2half2_rn(w0, w1);
    g_WkFH[t] = *(const uint32_t*)&h;
}

// ---------------------------------------------------------------------------
// Kernel C: M=256 x N=128 per CTA (512 threads) — gather computed ONCE per
//   pixel tile. Warp grid 4x4 (wm: 64 rows, wn: 32 cols). r11 loop skeleton.
// ---------------------------------------------------------------------------
__global__ __launch_bounds__(512, 1)
void dconv_mma_kernel(float* __restrict__ out) {
    extern __shared__ char dsm[];
    __shared__ __align__(16) int4  sOff[2][128];
    __shared__ __align__(16) uint4 sWh[2][128];

    uint32_t sb = (uint32_t)__cvta_generic_to_shared(dsm);

    int tid  = threadIdx.x;
    int lane = tid & 31;
    int wid  = tid >> 5;
    int bx = blockIdx.x;             // 0..255
    int b  = bx >> 5;
    int p0 = (bx & 31) * 128;

    int wm = wid & 3;                // M quarter (64 rows)
    int wn = wid >> 2;               // N quarter (32 cols)
    int hsel = lane >> 4;            // pixel parity within pair
    int lidx = lane & 15;            // channel quad

    float acc[4][4][4];
#pragma unroll
    for (int mi = 0; mi < 4; mi++)
#pragma unroll
        for (int ni = 0; ni < 4; ni++)
#pragma unroll
            for (int r = 0; r < 4; r++) acc[mi][ni][r] = 0.0f;

    const __half* xTb = g_xTh + (size_t)b * HWSZ * CC;

    // cp.async A: 512 threads x 4 uint4 = 32KB/slab; thread t covers
    // quarter t>>7, uint4s (t&127)*4 .. +4 of that quarter's 512-uint4 block.
    const uint4* asrc_base = (const uint4*)g_WkFH
        + (size_t)(tid >> 7) * NKB * 512 + (tid & 127) * 4;
    uint32_t adst_base = sb + AS_OFF +
        (uint32_t)(((tid >> 7) * 512 + (tid & 127) * 4) * 16);

    uint32_t aBase = sb + AS_OFF + (uint32_t)(wm * 8192) + (uint32_t)lane * 16;
    uint32_t bStsBase = sb + BS_OFF +
        (uint32_t)((((wid * 8 + hsel) * SW) + 2 * lidx) * 4);
    uint32_t bLdmBase = sb + BS_OFF + (uint32_t)(
        ((wn * 32 + ((lane >> 4) & 1) * 8 + (lane & 7)) * SW +
         ((lane >> 3) & 1) * 4) * 4);

    // ---- prologue: meta k2=0; cp.async A slab0; gather slab 0
    if (tid < 128) {
        size_t mi0 = ((size_t)(b * K2C) * HWSZ) + p0 + tid;
        sOff[0][tid] = g_off[mi0];
        sWh[0][tid]  = g_wh[mi0];
    }
#pragma unroll
    for (int it = 0; it < 4; it++)
        cpasync16(adst_base + it * 16, asrc_base + it);
    cpasync_commit();
    __syncthreads();
    {
        const char* xc = (const char*)xTb + lidx * 8;
#pragma unroll
        for (int q = 0; q < 4; q++) {
            int p = wid * 8 + 2 * q + hsel;
            int4  ov = sOff[0][p];
            uint4 wv = sWh[0][p];
            uint2 u0 = *(const uint2*)(xc + ov.x);
            uint2 u1 = *(const uint2*)(xc + ov.y);
            uint2 u2 = *(const uint2*)(xc + ov.z);
            uint2 u3 = *(const uint2*)(xc + ov.w);
            __half2 a0 = __hmul2(*(const __half2*)&wv.x, *(const __half2*)&u0.x);
            __half2 a1 = __hmul2(*(const __half2*)&wv.x, *(const __half2*)&u0.y);
            a0 = __hfma2(*(const __half2*)&wv.y, *(const __half2*)&u1.x, a0);
            a1 = __hfma2(*(const __half2*)&wv.y, *(const __half2*)&u1.y, a1);
            a0 = __hfma2(*(const __half2*)&wv.z, *(const __half2*)&u2.x, a0);
            a1 = __hfma2(*(const __half2*)&wv.z, *(const __half2*)&u2.y, a1);
            a0 = __hfma2(*(const __half2*)&wv.w, *(const __half2*)&u3.x, a0);
            a1 = __hfma2(*(const __half2*)&wv.w, *(const __half2*)&u3.y, a1);
            sts64(bStsBase + q * (2 * SW * 4),
                  *(const uint32_t*)&a0, *(const uint32_t*)&a1);
        }
    }
    cpasync_wait0();

    for (int kb = 0; kb < NKB; kb++) {
        __syncthreads();          // publishes B_s/A_s for kb (and prefetched meta)
        int nkb = kb + 1;
        int buf  = kb & 1;
        int nbuf = nkb & 1;
        bool more = (nkb < NKB);

        // prefetch meta two slabs ahead (visible via next iteration's sync)
        {
            int nm = kb + 2;
            if (nm < NKB && (nm & 3) == 0 && tid < 128) {
                int mk2 = nm >> 2;
                size_t mi0 = ((size_t)(b * K2C + mk2) * HWSZ) + p0 + tid;
                sOff[mk2 & 1][tid] = g_off[mi0];
                sWh[mk2 & 1][tid]  = g_wh[mi0];
            }
        }

        // cp.async A slab nkb
        if (more) {
            const uint4* asrc = asrc_base + (size_t)nkb * 512;
            uint32_t adst = adst_base + (uint32_t)(nbuf * A_STG);
#pragma unroll
            for (int it = 0; it < 4; it++)
                cpasync16(adst + it * 16, asrc + it);
            cpasync_commit();
        }

        int mb = more ? ((nkb >> 2) & 1) : 0;
        const char* xc = (const char*)(xTb + (more ? (nkb & 3) * 64 : 0)) + lidx * 8;
        uint32_t sB = bStsBase + (uint32_t)(nbuf * 18432);
        uint32_t aB = aBase + (uint32_t)(buf * A_STG);
        uint32_t bB = bLdmBase + (uint32_t)(buf * 18432);

        // ---- gather slab nkb into registers (overlaps MMA below)
        uint2 raw[16];
        if (more) {
#pragma unroll
            for (int q = 0; q < 4; q++) {
                int p = wid * 8 + 2 * q + hsel;
                int4 ov = sOff[mb][p];
                raw[q * 4 + 0] = *(const uint2*)(xc + ov.x);
                raw[q * 4 + 1] = *(const uint2*)(xc + ov.y);
                raw[q * 4 + 2] = *(const uint2*)(xc + ov.z);
                raw[q * 4 + 3] = *(const uint2*)(xc + ov.w);
            }
        }

        // ---- MMA on slab kb
#pragma unroll
        for (int ks = 0; ks < 4; ks++) {
            uint32_t bfr[4][2];
#pragma unroll
            for (int np = 0; np < 2; np++)
                ldmx4(bfr[np * 2][0], bfr[np * 2][1],
                      bfr[np * 2 + 1][0], bfr[np * 2 + 1][1],
                      bB + (uint32_t)(np * 2304 + ks * 32));
#pragma unroll
            for (int mi = 0; mi < 4; mi++) {
                uint4 afr = lds128(aB + (uint32_t)(((mi * 4 + ks) * 32) * 16));
#pragma unroll
                for (int ni = 0; ni < 4; ni++) {
                    asm volatile(
                        "mma.sync.aligned.m16n8k16.row.col.f32.f16.f16.f32 "
                        "{%0,%1,%2,%3}, {%4,%5,%6,%7}, {%8,%9}, {%0,%1,%2,%3};"
                        : "+f"(acc[mi][ni][0]), "+f"(acc[mi][ni][1]),
                          "+f"(acc[mi][ni][2]), "+f"(acc[mi][ni][3])
                        : "r"(afr.x), "r"(afr.y), "r"(afr.z), "r"(afr.w),
                          "r"(bfr[ni][0]), "r"(bfr[ni][1]));
                }
            }
        }

        // ---- combine + STS gathered slab nkb; wait its A
        if (more) {
#pragma unroll
            for (int q = 0; q < 4; q++) {
                int p = wid * 8 + 2 * q + hsel;
                uint4 wv = sWh[mb][p];
                uint2 u0 = raw[q * 4 + 0];
                uint2 u1 = raw[q * 4 + 1];
                uint2 u2 = raw[q * 4 + 2];
                uint2 u3 = raw[q * 4 + 3];
                __half2 a0 = __hmul2(*(const __half2*)&wv.x, *(const __half2*)&u0.x);
                __half2 a1 = __hmul2(*(const __half2*)&wv.x, *(const __half2*)&u0.y);
                a0 = __hfma2(*(const __half2*)&wv.y, *(const __half2*)&u1.x, a0);
                a1 = __hfma2(*(const __half2*)&wv.y, *(const __half2*)&u1.y, a1);
                a0 = __hfma2(*(const __half2*)&wv.z, *(const __half2*)&u2.x, a0);
                a1 = __hfma2(*(const __half2*)&wv.z, *(const __half2*)&u2.y, a1);
                a0 = __hfma2(*(const __half2*)&wv.w, *(const __half2*)&u3.x, a0);
                a1 = __hfma2(*(const __half2*)&wv.w, *(const __half2*)&u3.y, a1);
                sts64(sB + q * (2 * SW * 4),
                      *(const uint32_t*)&a0, *(const uint32_t*)&a1);
            }
            cpasync_wait0();
        }
    }

    // ---- epilogue: m = wm*64 + mi*16 + r; n = wn*32 + ni*8 + cl
    {
        int r  = lane >> 2;
        int cl = (lane & 3) * 2;
#pragma unroll
        for (int mi = 0; mi < 4; mi++) {
            int m = wm * 64 + mi * 16 + r;
            float* op = out + ((size_t)b * OO + m) * HWSZ + p0;
#pragma unroll
            for (int ni = 0; ni < 4; ni++) {
                int n = wn * 32 + ni * 8 + cl;
                *(float2*)(op + n) =
                    make_float2(acc[mi][ni][0], acc[mi][ni][1]);
                *(float2*)(op + 8 * HWSZ + n) =
                    make_float2(acc[mi][ni][2], acc[mi][ni][3]);
            }
        }
    }
}

// ---------------------------------------------------------------------------
extern "C" void kernel_launch(void* const* d_in, const int* in_sizes, int n_in,
                              void* d_out, int out_size) {
    const float* x      = (const float*)d_in[0];
    const float* offset = (const float*)d_in[1];
    const float* weight = (const float*)d_in[2];
    float* out = (float*)d_out;

    cudaFuncSetAttribute(dconv_mma_kernel,
                         cudaFuncAttributeMaxDynamicSharedMemorySize, DSMEM_BYTES);

    transpose_x_kernel<<<dim3(HWSZ / 32, CC / 32, BB), dim3(32, 8)>>>(x);
    build_meta_kernel<<<(BB * K2C * HWSZ) / 256, 256>>>(offset);
    prep_w_kernel<<<(OO * KTOT / 2) / 256, 256>>>(weight);
    dconv_mma_kernel<<<BB * 32, 512, DSMEM_BYTES>>>(out);
}